// round 3
// baseline (speedup 1.0000x reference)
#include <cuda_runtime.h>

// waspGridSpatialIntegral: out[:,0,:,:] = inclusive cumsum over width  (contiguous)
//                          out[:,1,:,:] = inclusive cumsum over height (stride-W)
// B=64, W=512, fp32. Memory-bound: 128 MiB read + 128 MiB write.
//
// y-scan: tile-based. One block owns a 512-row x 32-col strip of a channel-1
// plane. All global loads are independent (memcpy-like); the serial scan work
// happens in shared memory. x-scan: one warp per row, float4 traffic.

#define W     512
#define BATCH 64
#define TPAD  33                       // smem row stride (conflict-free)

#define YB (BATCH * (W / 32))          // 1024 y-strip blocks
#define XB ((BATCH * W * 32) / 256)    // 4096 x-scan blocks (1 warp / row)

#define SMEM_FLOATS (512 * TPAD + 16 * TPAD)
#define SMEM_BYTES  (SMEM_FLOATS * 4)  // 69696 B

__global__ __launch_bounds__(256) void wasp_integral_kernel(
    const float* __restrict__ in, float* __restrict__ out)
{
    extern __shared__ float sm[];
    float* tile = sm;                  // [512][TPAD]
    float* offs = sm + 512 * TPAD;     // [16][TPAD]

    if (blockIdx.x < YB) {
        // ---------------- y-scan strip: 512 rows x 32 cols ------------------
        const int b  = blockIdx.x >> 4;          // image
        const int c0 = (blockIdx.x & 15) << 5;   // column base of strip
        const size_t base = (size_t)(b * 2 + 1) * W * W + c0;  // channel 1
        const float* src = in + base;
        float*       dst = out + base;

        const int c   = threadIdx.x & 31;        // column within strip
        const int s0  = threadIdx.x >> 5;        // warp id / base segment

        // Phase 1: load strip gmem -> smem. 64 fully-independent coalesced
        // 128B warp-loads per thread-iteration; STS banks (r+c)%32 distinct.
        #pragma unroll
        for (int k = 0; k < 64; k++) {
            const int r = s0 + k * 8;
            tile[r * TPAD + c] = src[(size_t)r * W + c];
        }
        __syncthreads();

        // Phase 2: in-place inclusive scan of each 32-row segment.
        // Work item (c, s): 32 cols x 16 segs = 512 items, 2 per thread.
        #pragma unroll
        for (int p = 0; p < 2; p++) {
            const int s = s0 + p * 8;
            float sum = 0.0f;
            #pragma unroll
            for (int i = 0; i < 32; i++) {
                const int r = s * 32 + i;
                sum += tile[r * TPAD + c];
                tile[r * TPAD + c] = sum;
            }
        }
        __syncthreads();

        // Exclusive scan of the 16 segment totals, per column (32 threads).
        if (threadIdx.x < 32) {
            const int cc = threadIdx.x;
            float off = 0.0f;
            offs[cc] = 0.0f;
            #pragma unroll
            for (int s = 1; s < 16; s++) {
                off += tile[(s * 32 - 1) * TPAD + cc];
                offs[s * TPAD + cc] = off;
            }
        }
        __syncthreads();

        // Phase 3: add segment offset, store coalesced (128B per warp-row).
        #pragma unroll
        for (int p = 0; p < 2; p++) {
            const int s = s0 + p * 8;
            const float off = offs[s * TPAD + c];
            #pragma unroll
            for (int i = 0; i < 32; i++) {
                const int r = s * 32 + i;
                dst[(size_t)r * W + c] = tile[r * TPAD + c] + off;
            }
        }
    } else {
        // ---------------- x-scan: one warp per row --------------------------
        const int bx    = blockIdx.x - YB;
        const int gwarp = (bx * 256 + threadIdx.x) >> 5;  // [0, BATCH*W)
        const int lane  = threadIdx.x & 31;

        const int b = gwarp >> 9;
        const int y = gwarp & (W - 1);

        const size_t plane = (size_t)(b * 2) * W * W + (size_t)y * W;  // ch 0
        const float4* src = reinterpret_cast<const float4*>(in + plane) + lane * 4;
        float4*       dst = reinterpret_cast<float4*>(out + plane) + lane * 4;

        float4 a0 = src[0];
        float4 a1 = src[1];
        float4 a2 = src[2];
        float4 a3 = src[3];

        float v[16];
        v[0]=a0.x;  v[1]=a0.y;  v[2]=a0.z;  v[3]=a0.w;
        v[4]=a1.x;  v[5]=a1.y;  v[6]=a1.z;  v[7]=a1.w;
        v[8]=a2.x;  v[9]=a2.y;  v[10]=a2.z; v[11]=a2.w;
        v[12]=a3.x; v[13]=a3.y; v[14]=a3.z; v[15]=a3.w;

        #pragma unroll
        for (int i = 1; i < 16; i++) v[i] += v[i - 1];

        float total = v[15];
        float incl  = total;
        #pragma unroll
        for (int d = 1; d < 32; d <<= 1) {
            float n = __shfl_up_sync(0xFFFFFFFFu, incl, d);
            if (lane >= d) incl += n;
        }
        const float excl = incl - total;

        #pragma unroll
        for (int i = 0; i < 16; i++) v[i] += excl;

        dst[0] = make_float4(v[0],  v[1],  v[2],  v[3]);
        dst[1] = make_float4(v[4],  v[5],  v[6],  v[7]);
        dst[2] = make_float4(v[8],  v[9],  v[10], v[11]);
        dst[3] = make_float4(v[12], v[13], v[14], v[15]);
    }
}

extern "C" void kernel_launch(void* const* d_in, const int* in_sizes, int n_in,
                              void* d_out, int out_size)
{
    const float* in  = (const float*)d_in[0];
    float*       out = (float*)d_out;

    cudaFuncSetAttribute(wasp_integral_kernel,
                         cudaFuncAttributeMaxDynamicSharedMemorySize, SMEM_BYTES);
    wasp_integral_kernel<<<YB + XB, 256, SMEM_BYTES>>>(in, out);
}